// round 3
// baseline (speedup 1.0000x reference)
#include <cuda_runtime.h>

#define BB 8
#define CC 64
#define HH 128
#define WW 128
#define HWSZ (HH*WW)
#define KOFF 18

// scratch (no allocations allowed)
__device__ float g_offset[BB*KOFF*HWSZ];   // post-PReLU offsets [B,18,H,W]
__device__ float g_atten [BB*CC*HWSZ];     // softmax(conv) [B,64,H,W]
__device__ float g_xt    [BB*HWSZ*CC];     // x transposed to NHWC [B,H,W,C]

typedef unsigned long long u64;

__device__ __forceinline__ u64 pk2(float lo, float hi){
    u64 r; asm("mov.b64 %0, {%1,%2};" : "=l"(r) : "f"(lo), "f"(hi)); return r;
}
__device__ __forceinline__ float2 uf2(u64 v){
    float2 f; asm("mov.b64 {%0,%1}, %2;" : "=f"(f.x), "=f"(f.y) : "l"(v)); return f;
}
__device__ __forceinline__ u64 fma2(u64 a, u64 b, u64 c){
    u64 d; asm("fma.rn.f32x2 %0, %1, %2, %3;" : "=l"(d) : "l"(a), "l"(b), "l"(c)); return d;
}

// ---------------------------------------------------------------------------
// T: transpose x NCHW -> NHWC (g_xt). grid 1024 = (b,h), block 256.
// ---------------------------------------------------------------------------
__global__ __launch_bounds__(256) void k_transpose(const float* __restrict__ x)
{
    __shared__ float s[64][129];
    int t = threadIdx.x;
    int b = blockIdx.x >> 7, h = blockIdx.x & 127;
    const float* xb = x + b*CC*HWSZ + h*WW;
    for (int i = t; i < 64*128; i += 256) {
        int c = i >> 7, w = i & 127;
        s[c][w] = xb[c*HWSZ + w];
    }
    __syncthreads();
    float* ob = g_xt + (b*HH + h)*WW*CC;
    for (int i = t; i < 64*128; i += 256) {
        int w = i >> 6, c = i & 63;
        ob[w*CC + c] = s[c][w];
    }
}

// ---------------------------------------------------------------------------
// A: fused conv: 64 logit channels (-> softmax over W -> g_atten)
//    + 18 offset channels (-> +bias, PReLU -> g_offset).
// grid 1024 = (b,h); block 256 = 16 wq (8 px) x 16 grp.
// Every grp computes 4 logit oc + 1-2 offset oc (balanced).
// cin chunked by 8: small smem -> 2 blocks/SM.
// ---------------------------------------------------------------------------
__global__ __launch_bounds__(256, 2) void k_convA(
    const float* __restrict__ x,  const float* __restrict__ offw,
    const float* __restrict__ offb, const float* __restrict__ pa_,
    const float* __restrict__ cw)
{
    extern __shared__ float sm[];
    float* sxt = sm;                              // 8*3*132 floats
    u64*   scw = (u64*)(sm + 8*3*132);            // 64*8*9 dup'd logit weights
    u64*   sow = scw + 64*8*9;                    // 18*8*9 dup'd offset weights

    int t = threadIdx.x;
    int b = blockIdx.x >> 7, h = blockIdx.x & 127;
    int wq = t & 15, grp = t >> 4;
    int w0 = wq << 3;
    int ocount = (grp < 2) ? 2 : 1;
    int obase  = (grp < 2) ? grp*2 : grp + 2;     // covers 0..17

    u64 accL[4][4];
    u64 accO[2][4];
    #pragma unroll
    for (int o = 0; o < 4; o++)
        #pragma unroll
        for (int j = 0; j < 4; j++) accL[o][j] = 0ULL;
    #pragma unroll
    for (int j2 = 0; j2 < 2; j2++) {
        float bo = (j2 < ocount) ? offb[obase + j2] : 0.f;
        u64 bv = pk2(bo, bo);
        #pragma unroll
        for (int j = 0; j < 4; j++) accO[j2][j] = bv;
    }

    for (int ch = 0; ch < 8; ch++) {
        __syncthreads();
        // x subtile: 8 cin x rows h-1..h+1 x padded width 130 (stride 132)
        for (int i = t; i < 8*390; i += 256) {
            int c = i / 390; int rem = i - c*390;
            int r = rem / 130; int pc = rem - r*130;
            int iy = h + r - 1, iw = pc - 1;
            float v = 0.f;
            if (iy >= 0 && iy < HH && iw >= 0 && iw < WW)
                v = x[(b*CC + ch*8 + c)*HWSZ + iy*WW + iw];
            sxt[(c*3 + r)*132 + pc] = v;
        }
        for (int i = t; i < 64*8*9; i += 256) {
            int o = i / 72; int rem = i - o*72;
            float v = cw[(o*CC + ch*8)*9 + rem];
            scw[i] = pk2(v, v);
        }
        for (int i = t; i < 18*8*9; i += 256) {
            int o = i / 72; int rem = i - o*72;
            float v = offw[(o*CC + ch*8)*9 + rem];
            sow[i] = pk2(v, v);
        }
        __syncthreads();

        #pragma unroll 1
        for (int cl = 0; cl < 8; cl++) {
            #pragma unroll
            for (int ky = 0; ky < 3; ky++) {
                const float* xr = sxt + (cl*3 + ky)*132;
                float4 Av = *(const float4*)(xr + w0);
                float4 Bv = *(const float4*)(xr + w0 + 4);
                float2 Cv = *(const float2*)(xr + w0 + 8);
                u64 P[9];
                P[0] = pk2(Av.x, Av.y); P[1] = pk2(Av.y, Av.z);
                P[2] = pk2(Av.z, Av.w); P[3] = pk2(Av.w, Bv.x);
                P[4] = pk2(Bv.x, Bv.y); P[5] = pk2(Bv.y, Bv.z);
                P[6] = pk2(Bv.z, Bv.w); P[7] = pk2(Bv.w, Cv.x);
                P[8] = pk2(Cv.x, Cv.y);
                const u64* wrL = scw + (grp*4)*72 + cl*9 + ky*3;
                const u64* wrO = sow + obase*72 + cl*9 + ky*3;
                #pragma unroll
                for (int kx = 0; kx < 3; kx++) {
                    #pragma unroll
                    for (int o = 0; o < 4; o++) {
                        u64 wv = wrL[o*72 + kx];
                        #pragma unroll
                        for (int j = 0; j < 4; j++)
                            accL[o][j] = fma2(wv, P[kx + 2*j], accL[o][j]);
                    }
                    #pragma unroll
                    for (int j2 = 0; j2 < 2; j2++) {
                        if (j2 < ocount) {
                            u64 wv = wrO[j2*72 + kx];
                            #pragma unroll
                            for (int j = 0; j < 4; j++)
                                accO[j2][j] = fma2(wv, P[kx + 2*j], accO[j2][j]);
                        }
                    }
                }
            }
        }
    }

    // ---- logits: softmax over W, half-warp (16 lanes) owns a 128-px row ----
    #pragma unroll
    for (int o = 0; o < 4; o++) {
        int oc = grp*4 + o;
        float v[8];
        #pragma unroll
        for (int j = 0; j < 4; j++) {
            float2 u = uf2(accL[o][j]); v[2*j] = u.x; v[2*j + 1] = u.y;
        }
        float m = v[0];
        #pragma unroll
        for (int i = 1; i < 8; i++) m = fmaxf(m, v[i]);
        #pragma unroll
        for (int s = 1; s < 16; s <<= 1)
            m = fmaxf(m, __shfl_xor_sync(0xffffffffu, m, s));
        float e[8]; float smv = 0.f;
        #pragma unroll
        for (int i = 0; i < 8; i++) { e[i] = __expf(v[i] - m); smv += e[i]; }
        #pragma unroll
        for (int s = 1; s < 16; s <<= 1)
            smv += __shfl_xor_sync(0xffffffffu, smv, s);
        float inv = 1.0f / smv;
        int base = ((b*CC + oc)*HH + h)*WW + w0;
        *(float4*)&g_atten[base]     = make_float4(e[0]*inv, e[1]*inv, e[2]*inv, e[3]*inv);
        *(float4*)&g_atten[base + 4] = make_float4(e[4]*inv, e[5]*inv, e[6]*inv, e[7]*inv);
    }

    // ---- offsets: PReLU ----
    float pa = pa_[0];
    #pragma unroll
    for (int j2 = 0; j2 < 2; j2++) {
        if (j2 < ocount) {
            float v[8];
            #pragma unroll
            for (int j = 0; j < 4; j++) {
                float2 u = uf2(accO[j2][j]); v[2*j] = u.x; v[2*j + 1] = u.y;
            }
            #pragma unroll
            for (int i = 0; i < 8; i++) v[i] = v[i] >= 0.f ? v[i] : pa*v[i];
            int base = ((b*KOFF + obase + j2)*HH + h)*WW + w0;
            *(float4*)&g_offset[base]     = make_float4(v[0], v[1], v[2], v[3]);
            *(float4*)&g_offset[base + 4] = make_float4(v[4], v[5], v[6], v[7]);
        }
    }
}

// ---------------------------------------------------------------------------
// C: deformable grouped conv, direct NHWC gather, fused epilogue
//    out = atten*feat + x. grid 2048 = (b,h) x 2 group-halves, block 256 =
//    64 wp (2 px) x 4 groups. Per corner: 8 channels = 2x LDG.128 (one sector).
// ---------------------------------------------------------------------------
__global__ __launch_bounds__(256, 2) void k_deformC(
    const float* __restrict__ x, const float* __restrict__ dw,
    const float* __restrict__ db, float* __restrict__ out)
{
    extern __shared__ float smB[];
    float* soff = smB;                          // 18*128 floats
    u64*   swd  = (u64*)(smB + KOFF*WW);        // 4 groups * 8oc*8ci*9 dup'd

    int t = threadIdx.x;
    int bh = blockIdx.x >> 1;
    int b = bh >> 7, h = bh & 127;
    int ghalf = blockIdx.x & 1;

    for (int i = t; i < KOFF*WW; i += 256)
        soff[i] = g_offset[(b*KOFF + (i >> 7))*HWSZ + h*WW + (i & 127)];
    for (int i = t; i < 4*8*8*9; i += 256) {
        float v = dw[ghalf*(4*8*8*9) + i];
        swd[i] = pk2(v, v);
    }
    __syncthreads();

    int wp = t & 63, gl = t >> 6;
    int g = ghalf*4 + gl;
    int w0 = wp*2;

    u64 acc[8];
    #pragma unroll
    for (int o = 0; o < 8; o++) { float bo = db[g*8 + o]; acc[o] = pk2(bo, bo); }

    const float* xtb = g_xt + b*HWSZ*CC + g*8;

    #pragma unroll 1
    for (int k = 0; k < 9; k++) {
        int ky = k / 3, kx = k - ky*3;
        float s[2][8];
        #pragma unroll
        for (int p = 0; p < 2; p++) {
            int w = w0 + p;
            float dy = soff[(2*k)*WW + w];
            float dx = soff[(2*k + 1)*WW + w];
            float ys = (float)(h - 1 + ky) + dy;
            float xs = (float)(w - 1 + kx) + dx;
            float yf = floorf(ys), xf = floorf(xs);
            float ay = ys - yf, ax = xs - xf;
            int iy0 = (int)yf, ix0 = (int)xf;
            float my0 = (iy0 >= 0  && iy0 < HH)     ? 1.f : 0.f;
            float my1 = (iy0 >= -1 && iy0 + 1 < HH) ? 1.f : 0.f;
            float mx0 = (ix0 >= 0  && ix0 < WW)     ? 1.f : 0.f;
            float mx1 = (ix0 >= -1 && ix0 + 1 < WW) ? 1.f : 0.f;
            int cy0 = min(max(iy0, 0), HH - 1), cy1 = min(max(iy0 + 1, 0), HH - 1);
            int cx0 = min(max(ix0, 0), WW - 1), cx1 = min(max(ix0 + 1, 0), WW - 1);
            float c00 = (1.f - ay)*(1.f - ax)*my0*mx0;
            float c01 = (1.f - ay)*ax*my0*mx1;
            float c10 = ay*(1.f - ax)*my1*mx0;
            float c11 = ay*ax*my1*mx1;
            const float* pA = xtb + (cy0*WW + cx0)*CC;
            const float* pB = xtb + (cy0*WW + cx1)*CC;
            const float* pC = xtb + (cy1*WW + cx0)*CC;
            const float* pD = xtb + (cy1*WW + cx1)*CC;
            float4 A0 = *(const float4*)pA,       A1 = *(const float4*)(pA + 4);
            float4 B0 = *(const float4*)pB,       B1 = *(const float4*)(pB + 4);
            float4 C0 = *(const float4*)pC,       C1 = *(const float4*)(pC + 4);
            float4 D0 = *(const float4*)pD,       D1 = *(const float4*)(pD + 4);
            s[p][0] = c00*A0.x + c01*B0.x + c10*C0.x + c11*D0.x;
            s[p][1] = c00*A0.y + c01*B0.y + c10*C0.y + c11*D0.y;
            s[p][2] = c00*A0.z + c01*B0.z + c10*C0.z + c11*D0.z;
            s[p][3] = c00*A0.w + c01*B0.w + c10*C0.w + c11*D0.w;
            s[p][4] = c00*A1.x + c01*B1.x + c10*C1.x + c11*D1.x;
            s[p][5] = c00*A1.y + c01*B1.y + c10*C1.y + c11*D1.y;
            s[p][6] = c00*A1.z + c01*B1.z + c10*C1.z + c11*D1.z;
            s[p][7] = c00*A1.w + c01*B1.w + c10*C1.w + c11*D1.w;
        }
        const u64* wk = swd + (gl*64)*9 + k;
        #pragma unroll
        for (int ci = 0; ci < 8; ci++) {
            u64 av = pk2(s[0][ci], s[1][ci]);
            #pragma unroll
            for (int o = 0; o < 8; o++)
                acc[o] = fma2(wk[(o*8 + ci)*9], av, acc[o]);
        }
    }

    // ---- epilogue: out = atten*feat + x ----
    #pragma unroll
    for (int o = 0; o < 8; o++) {
        int oc = g*8 + o;
        float2 f = uf2(acc[o]);
        int base = ((b*CC + oc)*HH + h)*WW + w0;
        float2 at = *(const float2*)(g_atten + base);
        float2 xv = *(const float2*)(x + base);
        float2 ov = make_float2(fmaf(at.x, f.x, xv.x), fmaf(at.y, f.y, xv.y));
        *(float2*)(out + base) = ov;
    }
}

extern "C" void kernel_launch(void* const* d_in, const int* in_sizes, int n_in,
                              void* d_out, int out_size)
{
    const float* x    = (const float*)d_in[0];
    const float* offw = (const float*)d_in[1];
    const float* offb = (const float*)d_in[2];
    const float* pa   = (const float*)d_in[3];
    const float* dw   = (const float*)d_in[4];
    const float* db   = (const float*)d_in[5];
    const float* cw   = (const float*)d_in[6];
    float* out = (float*)d_out;

    const int smemA = 8*3*132*4 + (64*8*9 + 18*8*9)*8;   // 59904
    const int smemC = KOFF*WW*4 + 4*8*8*9*8;             // 27648

    cudaFuncSetAttribute(k_convA,   cudaFuncAttributeMaxDynamicSharedMemorySize, smemA);
    cudaFuncSetAttribute(k_deformC, cudaFuncAttributeMaxDynamicSharedMemorySize, smemC);

    k_transpose<<<1024, 256>>>(x);
    k_convA<<<1024, 256, smemA>>>(x, offw, offb, pa, cw);
    k_deformC<<<2048, 256, smemC>>>(x, dw, db, out);
}

// round 5
// speedup vs baseline: 1.8294x; 1.8294x over previous
#include <cuda_runtime.h>
#include <cuda_bf16.h>
#include <cstdint>

#define BB 8
#define CC 64
#define HH 128
#define WW 128
#define HWSZ (HH*WW)
#define KOFF 18

// ---- scratch (no allocations allowed) ----
__device__ float g_offset[BB*KOFF*HWSZ];   // post-PReLU offsets [B,18,H,W]
__device__ float g_atten [BB*CC*HWSZ];     // softmax(conv) [B,64,H,W]
__device__ float g_xt    [BB*HWSZ*CC];     // x transposed to NHWC [B,H,W,C]
__device__ __align__(16) __nv_bfloat16 g_Bimg[576*88]; // B weights [k=576][n=88] bf16
__device__ float g_dummy[1];

typedef unsigned long long u64;

__device__ __forceinline__ u64 pk2(float lo, float hi){
    u64 r; asm("mov.b64 %0, {%1,%2};" : "=l"(r) : "f"(lo), "f"(hi)); return r;
}
__device__ __forceinline__ float2 uf2(u64 v){
    float2 f; asm("mov.b64 {%0,%1}, %2;" : "=f"(f.x), "=f"(f.y) : "l"(v)); return f;
}
__device__ __forceinline__ u64 fma2(u64 a, u64 b, u64 c){
    u64 d; asm("fma.rn.f32x2 %0, %1, %2, %3;" : "=l"(d) : "l"(a), "l"(b), "l"(c)); return d;
}
__device__ __forceinline__ uint32_t smem_to_u32(const void* p){
    uint32_t a;
    asm("{ .reg .u64 t; cvta.to.shared.u64 t, %1; cvt.u32.u64 %0, t; }" : "=r"(a) : "l"(p));
    return a;
}

#define LDSM_X4(r, addr) \
    asm volatile("ldmatrix.sync.aligned.m8n8.x4.shared.b16 {%0,%1,%2,%3}, [%4];" \
        : "=r"((r)[0]),"=r"((r)[1]),"=r"((r)[2]),"=r"((r)[3]) : "r"(addr))
#define LDSM_X2T(r, addr) \
    asm volatile("ldmatrix.sync.aligned.m8n8.x2.trans.shared.b16 {%0,%1}, [%2];" \
        : "=r"((r)[0]),"=r"((r)[1]) : "r"(addr))

__device__ __forceinline__ void mma16816(float* d, const uint32_t* a, const uint32_t* b){
    asm volatile("mma.sync.aligned.m16n8k16.row.col.f32.bf16.bf16.f32 "
        "{%0,%1,%2,%3}, {%4,%5,%6,%7}, {%8,%9}, {%0,%1,%2,%3};"
        : "+f"(d[0]), "+f"(d[1]), "+f"(d[2]), "+f"(d[3])
        : "r"(a[0]), "r"(a[1]), "r"(a[2]), "r"(a[3]), "r"(b[0]), "r"(b[1]));
}

// smem layout for k_convMMA (bytes):
//   [0, 101376)        B weights [576][88] bf16 (row stride 176B, conflict-free)
//   [101376, +56160)   sx: 3 rows x 130 px x 64ch bf16, px stride 144B
//   sD (88x132 f32 = 46464B) aliases the sx region after the mainloop
#define BOFF  0
#define SXOFF 101376
#define SMEMM (101376 + 56160)

// ---------------------------------------------------------------------------
// prepB: B image [k=576][n=88], k = tap*64 + cin; n = oc (64 logits, 18 offs, 6 pad)
// ---------------------------------------------------------------------------
__global__ void k_prepB(const float* __restrict__ cw, const float* __restrict__ offw)
{
    int i = blockIdx.x*256 + threadIdx.x;
    if (i >= 576*88) return;
    int k = i / 88, n = i - k*88;
    int tap = k >> 6, cin = k & 63;
    float v = 0.f;
    if (n < 64)      v = cw [(n*CC + cin)*9 + tap];
    else if (n < 82) v = offw[((n - 64)*CC + cin)*9 + tap];
    g_Bimg[i] = __float2bfloat16(v);
}

__global__ void k_dummy() { if (threadIdx.x == 0) g_dummy[0] = 0.f; }

// ---------------------------------------------------------------------------
// T: transpose x NCHW -> NHWC (g_xt). grid 1024 = (b,h), block 256.
// ---------------------------------------------------------------------------
__global__ __launch_bounds__(256) void k_transpose(const float* __restrict__ x)
{
    __shared__ float s[64][129];
    int t = threadIdx.x;
    int b = blockIdx.x >> 7, h = blockIdx.x & 127;
    const float* xb = x + b*CC*HWSZ + h*WW;
    for (int i = t; i < 64*128; i += 256) {
        int c = i >> 7, w = i & 127;
        s[c][w] = xb[c*HWSZ + w];
    }
    __syncthreads();
    float* ob = g_xt + (b*HH + h)*WW*CC;
    for (int i = t; i < 64*128; i += 256) {
        int w = i >> 6, c = i & 63;
        ob[w*CC + c] = s[c][w];
    }
}

// ---------------------------------------------------------------------------
// convMMA: per (b,h) row, im2col GEMM on HMMA (mma.sync m16n8k16 bf16).
//   A[128px][576k] from staged x rows (ldmatrix.x4), B[576][88] (ldmatrix.x2.trans),
//   D[128][88] f32 in registers -> sD -> softmax (oc<64 -> g_atten) /
//   bias+PReLU (oc 64..81 -> g_offset).
// grid 1024 = (b,h), block 256 = 8 warps x 16 px rows.
// ---------------------------------------------------------------------------
__global__ __launch_bounds__(256, 1) void k_convMMA(
    const float* __restrict__ offb, const float* __restrict__ pa_)
{
    extern __shared__ char smem[];
    uint32_t sb = smem_to_u32(smem);
    int t = threadIdx.x, wid = t >> 5, lane = t & 31;
    int b = blockIdx.x >> 7, h = blockIdx.x & 127;

    // ---- copy B weights into smem ----
    {
        const uint4* src = (const uint4*)g_Bimg;
        uint4* dst = (uint4*)(smem + BOFF);
        for (int i = t; i < 101376/16; i += 256) dst[i] = src[i];
    }

    // ---- stage x rows h-1..h+1 as bf16, NHWC, padded (130 px, stride 144B) ----
    for (int i = t; i < 3*130*32; i += 256) {
        int rp = i >> 5, cp = i & 31;            // rp = r*130 + pxp, cp = channel pair
        int r = rp / 130, pxp = rp - r*130;
        int y = h + r - 1, xc = pxp - 1;
        float2 v = make_float2(0.f, 0.f);
        if (y >= 0 && y < HH && xc >= 0 && xc < WW)
            v = *(const float2*)(g_xt + ((size_t)(b*HH + y)*WW + xc)*CC + cp*2);
        uint32_t p;
        asm("cvt.rn.satfinite.bf16x2.f32 %0, %1, %2;" : "=r"(p) : "f"(v.y), "f"(v.x));
        *(uint32_t*)(smem + SXOFF + rp*144 + cp*4) = p;
    }
    __syncthreads();

    // ---- mainloop: 9 taps x 4 k16-steps x 11 n-tiles ----
    float acc[11][4];
    #pragma unroll
    for (int nt = 0; nt < 11; nt++)
        #pragma unroll
        for (int j = 0; j < 4; j++) acc[nt][j] = 0.f;

    uint32_t l15  = lane & 15;
    uint32_t hi16 = (uint32_t)(lane >> 4) * 16;
    uint32_t sxa  = sb + SXOFF;
    uint32_t ba   = sb + BOFF;

    #pragma unroll 1
    for (int tap = 0; tap < 9; tap++) {
        int ky = tap / 3, kx = tap - ky*3;
        uint32_t rowA = sxa + (uint32_t)(ky*130 + kx + wid*16 + (int)l15)*144 + hi16;
        uint32_t rowB = ba + (uint32_t)(tap*64 + (int)l15)*176;
        #pragma unroll
        for (int s = 0; s < 4; s++) {
            uint32_t a[4];
            LDSM_X4(a, rowA + s*32);
            uint32_t bA = rowB + (uint32_t)s*16*176;
            #pragma unroll
            for (int nt = 0; nt < 11; nt++) {
                uint32_t bf[2];
                LDSM_X2T(bf, bA + nt*16);
                mma16816(acc[nt], a, bf);
            }
        }
    }

    // ---- fragments -> sD[oc][px] (aliases sx region; sx dead now) ----
    __syncthreads();
    float* sD = (float*)(smem + SXOFF);
    {
        int n0 = (lane & 3)*2;
        int px = wid*16 + (lane >> 2);
        #pragma unroll
        for (int nt = 0; nt < 11; nt++) {
            int n = nt*8 + n0;
            sD[n*132 + px]           = acc[nt][0];
            sD[(n + 1)*132 + px]     = acc[nt][1];
            sD[n*132 + px + 8]       = acc[nt][2];
            sD[(n + 1)*132 + px + 8] = acc[nt][3];
        }
    }
    __syncthreads();

    // ---- epilogue: warp per oc (strided): softmax over 128 px, or bias+PReLU ----
    float pa = pa_[0];
    for (int oc = wid; oc < 82; oc += 8) {
        float v[4];
        #pragma unroll
        for (int j = 0; j < 4; j++) v[j] = sD[oc*132 + lane + 32*j];
        if (oc < 64) {
            float m = fmaxf(fmaxf(v[0], v[1]), fmaxf(v[2], v[3]));
            #pragma unroll
            for (int s = 16; s > 0; s >>= 1)
                m = fmaxf(m, __shfl_xor_sync(0xffffffffu, m, s));
            float e[4]; float sum = 0.f;
            #pragma unroll
            for (int j = 0; j < 4; j++) { e[j] = __expf(v[j] - m); sum += e[j]; }
            #pragma unroll
            for (int s = 16; s > 0; s >>= 1)
                sum += __shfl_xor_sync(0xffffffffu, sum, s);
            float inv = 1.0f / sum;
            int base = ((b*CC + oc)*HH + h)*WW + lane;
            #pragma unroll
            for (int j = 0; j < 4; j++) g_atten[base + 32*j] = e[j]*inv;
        } else {
            int o2 = oc - 64;
            float bo = offb[o2];
            int base = ((b*KOFF + o2)*HH + h)*WW + lane;
            #pragma unroll
            for (int j = 0; j < 4; j++) {
                float u = v[j] + bo;
                g_offset[base + 32*j] = u >= 0.f ? u : pa*u;
            }
        }
    }
}

// ---------------------------------------------------------------------------
// C: deformable grouped conv, direct NHWC gather, fused epilogue
//    out = atten*feat + x. grid 2048 = (b,h) x 2 group-halves, block 256.
// ---------------------------------------------------------------------------
__global__ __launch_bounds__(256, 2) void k_deformC(
    const float* __restrict__ x, const float* __restrict__ dw,
    const float* __restrict__ db, float* __restrict__ out)
{
    extern __shared__ float smB[];
    float* soff = smB;                          // 18*128 floats
    u64*   swd  = (u64*)(smB + KOFF*WW);        // 4 groups * 8oc*8ci*9 dup'd

    int t = threadIdx.x;
    int bh = blockIdx.x >> 1;
    int b = bh >> 7, h = bh & 127;
    int ghalf = blockIdx.x & 1;

    for (int i = t; i < KOFF*WW; i += 256)
        soff[i] = g_offset[(b*KOFF + (i >> 7))*HWSZ + h*WW + (i & 127)];
    for (int i = t; i < 4*8*8*9; i += 256) {
        float v = dw[ghalf*(4*8*8*9) + i];
        swd[i] = pk2(v, v);
    }
    __syncthreads();

    int wp = t & 63, gl = t >> 6;
    int g = ghalf*4 + gl;
    int w0 = wp*2;

    u64 acc[8];
    #pragma unroll
    for (int o = 0; o < 8; o++) { float bo = db[g*8 + o]; acc[o] = pk2(bo, bo); }

    const float* xtb = g_xt + (size_t)b*HWSZ*CC + g*8;

    #pragma unroll 1
    for (int k = 0; k < 9; k++) {
        int ky = k / 3, kx = k - ky*3;
        float s[2][8];
        #pragma unroll
        for (int p = 0; p < 2; p++) {
            int w = w0 + p;
            float dy = soff[(2*k)*WW + w];
            float dx = soff[(2*k + 1)*WW + w];
            float ys = (float)(h - 1 + ky) + dy;
            float xs = (float)(w - 1 + kx) + dx;
            float yf = floorf(ys), xf = floorf(xs);
            float ay = ys - yf, ax = xs - xf;
            int iy0 = (int)yf, ix0 = (int)xf;
            float my0 = (iy0 >= 0  && iy0 < HH)     ? 1.f : 0.f;
            float my1 = (iy0 >= -1 && iy0 + 1 < HH) ? 1.f : 0.f;
            float mx0 = (ix0 >= 0  && ix0 < WW)     ? 1.f : 0.f;
            float mx1 = (ix0 >= -1 && ix0 + 1 < WW) ? 1.f : 0.f;
            int cy0 = min(max(iy0, 0), HH - 1), cy1 = min(max(iy0 + 1, 0), HH - 1);
            int cx0 = min(max(ix0, 0), WW - 1), cx1 = min(max(ix0 + 1, 0), WW - 1);
            float c00 = (1.f - ay)*(1.f - ax)*my0*mx0;
            float c01 = (1.f - ay)*ax*my0*mx1;
            float c10 = ay*(1.f - ax)*my1*mx0;
            float c11 = ay*ax*my1*mx1;
            const float* pA = xtb + (cy0*WW + cx0)*CC;
            const float* pB = xtb + (cy0*WW + cx1)*CC;
            const float* pC = xtb + (cy1*WW + cx0)*CC;
            const float* pD = xtb + (cy1*WW + cx1)*CC;
            float4 A0 = *(const float4*)pA,       A1 = *(const float4*)(pA + 4);
            float4 B0 = *(const float4*)pB,       B1 = *(const float4*)(pB + 4);
            float4 C0 = *(const float4*)pC,       C1 = *(const float4*)(pC + 4);
            float4 D0 = *(const float4*)pD,       D1 = *(const float4*)(pD + 4);
            s[p][0] = c00*A0.x + c01*B0.x + c10*C0.x + c11*D0.x;
            s[p][1] = c00*A0.y + c01*B0.y + c10*C0.y + c11*D0.y;
            s[p][2] = c00*A0.z + c01*B0.z + c10*C0.z + c11*D0.z;
            s[p][3] = c00*A0.w + c01*B0.w + c10*C0.w + c11*D0.w;
            s[p][4] = c00*A1.x + c01*B1.x + c10*C1.x + c11*D1.x;
            s[p][5] = c00*A1.y + c01*B1.y + c10*C1.y + c11*D1.y;
            s[p][6] = c00*A1.z + c01*B1.z + c10*C1.z + c11*D1.z;
            s[p][7] = c00*A1.w + c01*B1.w + c10*C1.w + c11*D1.w;
        }
        const u64* wk = swd + (gl*64)*9 + k;
        #pragma unroll
        for (int ci = 0; ci < 8; ci++) {
            u64 av = pk2(s[0][ci], s[1][ci]);
            #pragma unroll
            for (int o = 0; o < 8; o++)
                acc[o] = fma2(wk[(o*8 + ci)*9], av, acc[o]);
        }
    }

    #pragma unroll
    for (int o = 0; o < 8; o++) {
        int oc = g*8 + o;
        float2 f = uf2(acc[o]);
        int base = ((b*CC + oc)*HH + h)*WW + w0;
        float2 at = *(const float2*)(g_atten + base);
        float2 xv = *(const float2*)(x + base);
        float2 ov = make_float2(fmaf(at.x, f.x, xv.x), fmaf(at.y, f.y, xv.y));
        *(float2*)(out + base) = ov;
    }
}

extern "C" void kernel_launch(void* const* d_in, const int* in_sizes, int n_in,
                              void* d_out, int out_size)
{
    const float* x    = (const float*)d_in[0];
    const float* offw = (const float*)d_in[1];
    const float* offb = (const float*)d_in[2];
    const float* pa   = (const float*)d_in[3];
    const float* dw   = (const float*)d_in[4];
    const float* db   = (const float*)d_in[5];
    const float* cw   = (const float*)d_in[6];
    float* out = (float*)d_out;

    const int smemC = KOFF*WW*4 + 4*8*8*9*8;             // 27648

    cudaFuncSetAttribute(k_convMMA, cudaFuncAttributeMaxDynamicSharedMemorySize, SMEMM);
    cudaFuncSetAttribute(k_deformC, cudaFuncAttributeMaxDynamicSharedMemorySize, smemC);

    k_prepB<<<198, 256>>>(cw, offw);
    k_transpose<<<1024, 256>>>(x);
    k_convMMA<<<1024, 256, SMEMM>>>(offb, pa);
    k_dummy<<<1, 32>>>();
    k_dummy<<<1, 32>>>();
    k_deformC<<<2048, 256, smemC>>>(x, dw, db, out);   // launch #6 -> ncu capture
}